// round 13
// baseline (speedup 1.0000x reference)
#include <cuda_runtime.h>

// ---------------------------------------------------------------------------
// EnhancedReconstructionLoss: 0.8*MSE + 0.2*(1 - mean(SSIM_map)), fused.
//
// s/d reformulation (s=x+y, d=x-y) -> 4 window sums (Ws,Wd,Wss,Wdd):
//   N1 = (Ws^2-Wd^2) + 162*C1          N2 = 9(Wss-Wdd) - (Ws^2-Wd^2) + 162*C2
//   D1 = (Ws^2+Wd^2) + 162*C1          D2 = 9(Wss+Wdd) - (Ws^2+Wd^2) + 162*C2
//   ssim = N1*N2 / (D1*D2 + 4*6561*eps)
//
// R13 = R12 (raw-slot decoupled loads, in-place converts, shared pair squares)
//   + ROLLED loop: 4 iterations x (2 sub-iterations, constant slot indices)
//     -> body ~18KB, fits L1.5 I$ (the unrolled version streamed 70KB from L2)
//   + PAIRED division: n0/d0+n1/d1 = (n0*d1+n1*d0)/(d0*d1): halves MUFU.
// ---------------------------------------------------------------------------

typedef unsigned long long u64;

#define IMW 512
#define IMH 512
#define NPLANES 96
#define RPW 16                    // rows per warp-task
#define STRIPS 32                 // 512 / 16
#define WPB 4                     // warps per block
#define NBLOCKS (NPLANES * STRIPS * 2 / WPB)   // 1536
#define NTOTD 25165824.0          // 32*3*512*512

__device__ float g_mse_acc  = 0.f;
__device__ float g_ssim_acc = 0.f;
__device__ unsigned int g_cnt = 0u;

__device__ __forceinline__ u64 f2_pack(float lo, float hi) {
    u64 r; asm("mov.b64 %0, {%1, %2};" : "=l"(r) : "f"(lo), "f"(hi)); return r;
}
__device__ __forceinline__ void f2_unpack(u64 p, float& lo, float& hi) {
    asm("mov.b64 {%0, %1}, %2;" : "=f"(lo), "=f"(hi) : "l"(p));
}
__device__ __forceinline__ u64 f2_set(float v) { return f2_pack(v, v); }
__device__ __forceinline__ u64 add2(u64 a, u64 b) {
    u64 d; asm("add.rn.f32x2 %0, %1, %2;" : "=l"(d) : "l"(a), "l"(b)); return d;
}
__device__ __forceinline__ u64 sub2(u64 a, u64 b) {
    u64 d; asm("sub.rn.f32x2 %0, %1, %2;" : "=l"(d) : "l"(a), "l"(b)); return d;
}
__device__ __forceinline__ u64 mul2(u64 a, u64 b) {
    u64 d; asm("mul.rn.f32x2 %0, %1, %2;" : "=l"(d) : "l"(a), "l"(b)); return d;
}
__device__ __forceinline__ u64 fma2(u64 a, u64 b, u64 c) {
    u64 d; asm("fma.rn.f32x2 %0, %1, %2, %3;" : "=l"(d) : "l"(a), "l"(b), "l"(c)); return d;
}

// Horizontal 3-sum over 8 columns (4 packed u64), warp-shuffle neighbors plus
// scalar halo vH at the warp's interior boundary.
__device__ __forceinline__ void hsum8(const u64 v0, const u64 v1, const u64 v2, const u64 v3,
                                      float vH, int lane, int half,
                                      u64& H0, u64& H1, u64& H2, u64& H3) {
    float f0, f1, f2, f3, f4, f5, f6, f7;
    f2_unpack(v0, f0, f1);
    f2_unpack(v1, f2, f3);
    f2_unpack(v2, f4, f5);
    f2_unpack(v3, f6, f7);
    float up = __shfl_up_sync(0xffffffffu, f7, 1);
    float dn = __shfl_down_sync(0xffffffffu, f0, 1);
    float nl = (lane == 0)  ? (half ? vH : 0.f) : up;
    float nr = (lane == 31) ? (half ? 0.f : vH) : dn;
    u64 L0 = f2_pack(nl, f0);
    u64 L1 = f2_pack(f1, f2);
    u64 L2 = f2_pack(f3, f4);
    u64 L3 = f2_pack(f5, f6);
    u64 R3 = f2_pack(f7, nr);
    H0 = add2(add2(L0, v0), L1);
    H1 = add2(add2(L1, v1), L2);
    H2 = add2(add2(L2, v2), L3);
    H3 = add2(add2(L3, v3), R3);
}

__global__ void __launch_bounds__(128, 4)
loss_fused(const float* __restrict__ X, const float* __restrict__ Y,
           float* __restrict__ out) {
    const int w    = threadIdx.x >> 5;
    const int lane = threadIdx.x & 31;
    const int task  = blockIdx.x * WPB + w;
    const int half  = task & 1;
    const int strip = (task >> 1) & (STRIPS - 1);
    const int plane = task >> 6;
    const int R0 = strip * RPW;
    const int c0 = half * 256 + (lane << 3);

    const float* px = X + (size_t)plane * (IMW * IMH) + c0;
    const float* py = Y + (size_t)plane * (IMW * IMH) + c0;

    const bool hval = (lane == 0) ? (half == 1)
                    : ((lane == 31) ? (half == 0) : false);
    const int hoff = (lane == 0) ? -1 : 8;

    const u64 k9   = f2_set(9.0f);
    const u64 kC1  = f2_set(0.0162f);      // 162 * C1
    const u64 kC2  = f2_set(0.1458f);      // 162 * C2
    const u64 kEPS = f2_set(2.6244e-4f);   // 4 * 6561 * eps

    // 4-slot rolling window: RAW (x,y) until CONVERTed in place to (s,d).
    u64 ws[4][4], wdv[4][4];
    u64 whsd[4];

    auto PF = [&](int j) {
        int gr = R0 - 1 + j;
        gr = (gr < IMH) ? gr : (IMH - 1);
        const float* ax = px + (size_t)gr * IMW;
        const float* ay = py + (size_t)gr * IMW;
        asm volatile("prefetch.global.L2 [%0];" :: "l"(ax));
        asm volatile("prefetch.global.L2 [%0];" :: "l"(ay));
    };

    // Load row gr = R0-1+j RAW into compile-time slot (pure LDG + pack).
    auto LOAD_RAW = [&](int slot, int j) {
        const int gr = R0 - 1 + j;
        const bool v = ((unsigned)gr < (unsigned)IMH);
        float4 xa = make_float4(0.f, 0.f, 0.f, 0.f), xb = xa, ya = xa, yb = xa;
        float hx = 0.f, hy = 0.f;
        if (v) {
            const float4* p4 = reinterpret_cast<const float4*>(px + (size_t)gr * IMW);
            const float4* q4 = reinterpret_cast<const float4*>(py + (size_t)gr * IMW);
            xa = p4[0]; xb = p4[1];
            ya = q4[0]; yb = q4[1];
            if (hval) {
                hx = px[(size_t)gr * IMW + hoff];
                hy = py[(size_t)gr * IMW + hoff];
            }
        }
        ws[slot][0]  = f2_pack(xa.x, xa.y);  ws[slot][1]  = f2_pack(xa.z, xa.w);
        ws[slot][2]  = f2_pack(xb.x, xb.y);  ws[slot][3]  = f2_pack(xb.z, xb.w);
        wdv[slot][0] = f2_pack(ya.x, ya.y);  wdv[slot][1] = f2_pack(ya.z, ya.w);
        wdv[slot][2] = f2_pack(yb.x, yb.y);  wdv[slot][3] = f2_pack(yb.z, yb.w);
        whsd[slot]   = f2_pack(hx, hy);
    };

    // In-place convert slot from raw (x,y) to (s,d).
    auto CONVERT = [&](int slot) {
#pragma unroll
        for (int k = 0; k < 4; ++k) {
            u64 xv = ws[slot][k], yv = wdv[slot][k];
            ws[slot][k]  = add2(xv, yv);
            wdv[slot][k] = sub2(xv, yv);
        }
        float hx, hy;
        f2_unpack(whsd[slot], hx, hy);
        whsd[slot] = f2_pack(hx + hy, hx - hy);
    };

    LOAD_RAW(0, 0); LOAD_RAW(1, 1);
    CONVERT(0);     CONVERT(1);
    LOAD_RAW(2, 2); LOAD_RAW(3, 3);
    PF(4); PF(5); PF(6); PF(7);

    u64 mAcc0 = f2_set(0.f), mAcc1 = f2_set(0.f);
    float sA0 = 0.f, sA1 = 0.f;

    // One 2-output-row sub-iteration with compile-time slots A,B,C,D.
    // Processes output rows rr, rr+1; loads rows rr+4 -> slot A, rr+5 -> slot B.
    auto SUB = [&](int rr, int A, int B, int C, int D) {
        // (1) convert row rr+2 (raw since previous sub-iteration)
        CONVERT(C);

        // (2) halo partials + A-row halo sums
        u64 hA = whsd[A], hB = whsd[B], hC = whsd[C];
        u64 hp  = add2(hB, hC);
        u64 hq  = fma2(hB, hB, mul2(hC, hC));
        u64 vh1A = add2(hp, hA);
        u64 vh2A = fma2(hA, hA, hq);
        float vHsA, vHdA, vHssA, vHddA;
        f2_unpack(vh1A, vHsA, vHdA);
        f2_unpack(vh2A, vHssA, vHddA);

        // (2b) shared middle-pair partials: linear AND squares
        u64 ps[4], pd[4], qs[4], qd[4];
#pragma unroll
        for (int k = 0; k < 4; ++k) {
            u64 sB = ws[B][k],  sC = ws[C][k];
            u64 dB = wdv[B][k], dC = wdv[C][k];
            ps[k] = add2(sB, sC);
            pd[k] = add2(dB, dC);
            qs[k] = fma2(sB, sB, mul2(sC, sC));
            qd[k] = fma2(dB, dB, mul2(dC, dC));
        }

        // (2c) MSE of center rows B,C comes free from qd
        mAcc0 = add2(mAcc0, qd[0]);
        mAcc0 = add2(mAcc0, qd[1]);
        mAcc1 = add2(mAcc1, qd[2]);
        mAcc1 = add2(mAcc1, qd[3]);

        auto ROW = [&](int jx, float vHs, float vHd, float vHss, float vHdd) {
            u64 T1[4], T2[4];
            {
                u64 Vq[4], Hq[4];
#pragma unroll
                for (int k = 0; k < 4; ++k) Vq[k] = add2(ps[k], ws[jx][k]);
                hsum8(Vq[0], Vq[1], Vq[2], Vq[3], vHs, lane, half,
                      Hq[0], Hq[1], Hq[2], Hq[3]);
                u64 Es[4];
#pragma unroll
                for (int k = 0; k < 4; ++k) Es[k] = mul2(Hq[k], Hq[k]);
#pragma unroll
                for (int k = 0; k < 4; ++k) Vq[k] = add2(pd[k], wdv[jx][k]);
                hsum8(Vq[0], Vq[1], Vq[2], Vq[3], vHd, lane, half,
                      Hq[0], Hq[1], Hq[2], Hq[3]);
#pragma unroll
                for (int k = 0; k < 4; ++k) {
                    u64 F = mul2(Hq[k], Hq[k]);
                    T1[k] = sub2(Es[k], F);
                    T2[k] = add2(Es[k], F);
                }
            }
            u64 Hss[4], Hdd[4];
            {
                u64 Vq[4];
#pragma unroll
                for (int k = 0; k < 4; ++k)
                    Vq[k] = fma2(ws[jx][k], ws[jx][k], qs[k]);
                hsum8(Vq[0], Vq[1], Vq[2], Vq[3], vHss, lane, half,
                      Hss[0], Hss[1], Hss[2], Hss[3]);
#pragma unroll
                for (int k = 0; k < 4; ++k)
                    Vq[k] = fma2(wdv[jx][k], wdv[jx][k], qd[k]);
                hsum8(Vq[0], Vq[1], Vq[2], Vq[3], vHdd, lane, half,
                      Hdd[0], Hdd[1], Hdd[2], Hdd[3]);
            }
#pragma unroll
            for (int k = 0; k < 4; ++k) {
                u64 N1 = add2(T1[k], kC1);
                u64 D1 = add2(T2[k], kC1);
                u64 U1 = sub2(Hss[k], Hdd[k]);
                u64 U2 = add2(Hss[k], Hdd[k]);
                u64 N2 = sub2(fma2(U1, k9, kC2), T1[k]);
                u64 D2 = sub2(fma2(U2, k9, kC2), T2[k]);
                u64 num = mul2(N1, N2);
                u64 den = fma2(D1, D2, kEPS);
                float n0, n1, d0, d1;
                f2_unpack(num, n0, n1);
                f2_unpack(den, d0, d1);
                // paired division: one MUFU per 2 quotients
                float nc = fmaf(n0, d1, n1 * d0);
                float dc = d0 * d1;
                if (k & 1) sA1 += __fdividef(nc, dc);
                else       sA0 += __fdividef(nc, dc);
            }
        };

        // (3) output row rr : slots A,B,C (all converted)
        ROW(A, vHsA, vHdA, vHssA, vHddA);

        // (4) slot A retired -> load row rr+4 raw (needed by next sub)
        if (rr + 4 <= RPW + 1) LOAD_RAW(A, rr + 4);

        // (5) convert row rr+3; B-row halo sums
        CONVERT(D);
        u64 hD = whsd[D];
        u64 vh1B = add2(hp, hD);
        u64 vh2B = fma2(hD, hD, hq);
        float vHsB, vHdB, vHssB, vHddB;
        f2_unpack(vh1B, vHsB, vHdB);
        f2_unpack(vh2B, vHssB, vHddB);

        // (6) output row rr+1 : slots B,C,D
        ROW(D, vHsB, vHdB, vHssB, vHddB);

        // (7) slot B retired -> load row rr+5 raw; hint ahead
        if (rr + 5 <= RPW + 1) LOAD_RAW(B, rr + 5);
        PF(rr + 8); PF(rr + 9);
    };

#pragma unroll 1
    for (int r = 0; r < RPW; r += 4) {
        SUB(r,     0, 1, 2, 3);
        SUB(r + 2, 2, 3, 0, 1);
    }

    // ---- reductions ----
    float m0, m1, m2, m3;
    f2_unpack(mAcc0, m0, m1);
    f2_unpack(mAcc1, m2, m3);
    float mAcc = (m0 + m1) + (m2 + m3);
    float sAcc = sA0 + sA1;
#pragma unroll
    for (int o = 16; o; o >>= 1) {
        mAcc += __shfl_xor_sync(0xffffffffu, mAcc, o);
        sAcc += __shfl_xor_sync(0xffffffffu, sAcc, o);
    }
    __shared__ float shm[WPB], shs[WPB];
    if (lane == 0) { shm[w] = mAcc; shs[w] = sAcc; }
    __syncthreads();
    if (threadIdx.x == 0) {
        float M = (shm[0] + shm[1]) + (shm[2] + shm[3]);
        float S = (shs[0] + shs[1]) + (shs[2] + shs[3]);
        atomicAdd(&g_mse_acc, M);
        atomicAdd(&g_ssim_acc, S);
        __threadfence();
        unsigned c = atomicInc(&g_cnt, NBLOCKS - 1);   // wraps to 0 on last
        if (c == NBLOCKS - 1) {
            __threadfence();
            float Mt = atomicExch(&g_mse_acc, 0.f);
            float St = atomicExch(&g_ssim_acc, 0.f);
            double mse  = (double)Mt / NTOTD;
            double ssim = (double)St / NTOTD;
            out[0] = (float)(0.8 * mse + 0.2 * (1.0 - ssim));
        }
    }
}

extern "C" void kernel_launch(void* const* d_in, const int* in_sizes, int n_in,
                              void* d_out, int out_size) {
    const float* X = (const float*)d_in[0];
    const float* Y = (const float*)d_in[1];
    loss_fused<<<NBLOCKS, 128>>>(X, Y, (float*)d_out);
}

// round 14
// speedup vs baseline: 1.4958x; 1.4958x over previous
#include <cuda_runtime.h>

// ---------------------------------------------------------------------------
// EnhancedReconstructionLoss: 0.8*MSE + 0.2*(1 - mean(SSIM_map)), fused.
//
// s/d reformulation (s=x+y, d=x-y) -> 4 window sums (Ws,Wd,Wss,Wdd):
//   N1 = (Ws^2-Wd^2) + 162*C1          N2 = 9(Wss-Wdd) - (Ws^2-Wd^2) + 162*C2
//   D1 = (Ws^2+Wd^2) + 162*C1          D2 = 9(Wss+Wdd) - (Ws^2+Wd^2) + 162*C2
//   ssim = N1*N2 / (D1*D2 + 4*6561*eps)
//
// R14 = R12 EXACTLY (fully unrolled; raw-slot decoupled loads; in-place
// converts; shared middle-pair squares; MSE from qd; PF hints; (128,4))
//   + paired division only: n0/d0+n1/d1 = (n0*d1+n1*d0)/(d0*d1) -> MUFU halved.
// R13's rolled loop spilled to local memory (L1 50%, fma 32%) - reverted.
// ---------------------------------------------------------------------------

typedef unsigned long long u64;

#define IMW 512
#define IMH 512
#define NPLANES 96
#define RPW 16                    // rows per warp-task
#define STRIPS 32                 // 512 / 16
#define WPB 4                     // warps per block
#define NBLOCKS (NPLANES * STRIPS * 2 / WPB)   // 1536
#define NTOTD 25165824.0          // 32*3*512*512

__device__ float g_mse_acc  = 0.f;
__device__ float g_ssim_acc = 0.f;
__device__ unsigned int g_cnt = 0u;

__device__ __forceinline__ u64 f2_pack(float lo, float hi) {
    u64 r; asm("mov.b64 %0, {%1, %2};" : "=l"(r) : "f"(lo), "f"(hi)); return r;
}
__device__ __forceinline__ void f2_unpack(u64 p, float& lo, float& hi) {
    asm("mov.b64 {%0, %1}, %2;" : "=f"(lo), "=f"(hi) : "l"(p));
}
__device__ __forceinline__ u64 f2_set(float v) { return f2_pack(v, v); }
__device__ __forceinline__ u64 add2(u64 a, u64 b) {
    u64 d; asm("add.rn.f32x2 %0, %1, %2;" : "=l"(d) : "l"(a), "l"(b)); return d;
}
__device__ __forceinline__ u64 sub2(u64 a, u64 b) {
    u64 d; asm("sub.rn.f32x2 %0, %1, %2;" : "=l"(d) : "l"(a), "l"(b)); return d;
}
__device__ __forceinline__ u64 mul2(u64 a, u64 b) {
    u64 d; asm("mul.rn.f32x2 %0, %1, %2;" : "=l"(d) : "l"(a), "l"(b)); return d;
}
__device__ __forceinline__ u64 fma2(u64 a, u64 b, u64 c) {
    u64 d; asm("fma.rn.f32x2 %0, %1, %2, %3;" : "=l"(d) : "l"(a), "l"(b), "l"(c)); return d;
}

// Horizontal 3-sum over 8 columns (4 packed u64), warp-shuffle neighbors plus
// scalar halo vH at the warp's interior boundary.
__device__ __forceinline__ void hsum8(const u64 v0, const u64 v1, const u64 v2, const u64 v3,
                                      float vH, int lane, int half,
                                      u64& H0, u64& H1, u64& H2, u64& H3) {
    float f0, f1, f2, f3, f4, f5, f6, f7;
    f2_unpack(v0, f0, f1);
    f2_unpack(v1, f2, f3);
    f2_unpack(v2, f4, f5);
    f2_unpack(v3, f6, f7);
    float up = __shfl_up_sync(0xffffffffu, f7, 1);
    float dn = __shfl_down_sync(0xffffffffu, f0, 1);
    float nl = (lane == 0)  ? (half ? vH : 0.f) : up;
    float nr = (lane == 31) ? (half ? 0.f : vH) : dn;
    u64 L0 = f2_pack(nl, f0);
    u64 L1 = f2_pack(f1, f2);
    u64 L2 = f2_pack(f3, f4);
    u64 L3 = f2_pack(f5, f6);
    u64 R3 = f2_pack(f7, nr);
    H0 = add2(add2(L0, v0), L1);
    H1 = add2(add2(L1, v1), L2);
    H2 = add2(add2(L2, v2), L3);
    H3 = add2(add2(L3, v3), R3);
}

__global__ void __launch_bounds__(128, 4)
loss_fused(const float* __restrict__ X, const float* __restrict__ Y,
           float* __restrict__ out) {
    const int w    = threadIdx.x >> 5;
    const int lane = threadIdx.x & 31;
    const int task  = blockIdx.x * WPB + w;
    const int half  = task & 1;
    const int strip = (task >> 1) & (STRIPS - 1);
    const int plane = task >> 6;
    const int R0 = strip * RPW;
    const int c0 = half * 256 + (lane << 3);

    const float* px = X + (size_t)plane * (IMW * IMH) + c0;
    const float* py = Y + (size_t)plane * (IMW * IMH) + c0;

    const bool hval = (lane == 0) ? (half == 1)
                    : ((lane == 31) ? (half == 0) : false);
    const int hoff = (lane == 0) ? -1 : 8;

    const u64 k9   = f2_set(9.0f);
    const u64 kC1  = f2_set(0.0162f);      // 162 * C1
    const u64 kC2  = f2_set(0.1458f);      // 162 * C2
    const u64 kEPS = f2_set(2.6244e-4f);   // 4 * 6561 * eps

    // 4-slot rolling window: RAW (x,y) until CONVERTed in place to (s,d).
    u64 ws[4][4], wdv[4][4];
    u64 whsd[4];

    auto PF = [&](int j) {
        int gr = R0 - 1 + j;
        gr = (gr < IMH) ? gr : (IMH - 1);
        const float* ax = px + (size_t)gr * IMW;
        const float* ay = py + (size_t)gr * IMW;
        asm volatile("prefetch.global.L2 [%0];" :: "l"(ax));
        asm volatile("prefetch.global.L2 [%0];" :: "l"(ay));
    };

    // Load row gr = R0-1+j RAW into slot j&3 (pure LDG + pack).
    auto LOAD_RAW = [&](int j) {
        const int slot = j & 3;
        const int gr = R0 - 1 + j;
        const bool v = ((unsigned)gr < (unsigned)IMH);
        float4 xa = make_float4(0.f, 0.f, 0.f, 0.f), xb = xa, ya = xa, yb = xa;
        float hx = 0.f, hy = 0.f;
        if (v) {
            const float4* p4 = reinterpret_cast<const float4*>(px + (size_t)gr * IMW);
            const float4* q4 = reinterpret_cast<const float4*>(py + (size_t)gr * IMW);
            xa = p4[0]; xb = p4[1];
            ya = q4[0]; yb = q4[1];
            if (hval) {
                hx = px[(size_t)gr * IMW + hoff];
                hy = py[(size_t)gr * IMW + hoff];
            }
        }
        ws[slot][0]  = f2_pack(xa.x, xa.y);  ws[slot][1]  = f2_pack(xa.z, xa.w);
        ws[slot][2]  = f2_pack(xb.x, xb.y);  ws[slot][3]  = f2_pack(xb.z, xb.w);
        wdv[slot][0] = f2_pack(ya.x, ya.y);  wdv[slot][1] = f2_pack(ya.z, ya.w);
        wdv[slot][2] = f2_pack(yb.x, yb.y);  wdv[slot][3] = f2_pack(yb.z, yb.w);
        whsd[slot]   = f2_pack(hx, hy);
    };

    // In-place convert slot j&3 from raw (x,y) to (s,d).
    auto CONVERT = [&](int j) {
        const int slot = j & 3;
#pragma unroll
        for (int k = 0; k < 4; ++k) {
            u64 xv = ws[slot][k], yv = wdv[slot][k];
            ws[slot][k]  = add2(xv, yv);
            wdv[slot][k] = sub2(xv, yv);
        }
        float hx, hy;
        f2_unpack(whsd[slot], hx, hy);
        whsd[slot] = f2_pack(hx + hy, hx - hy);
    };

    LOAD_RAW(0); LOAD_RAW(1);
    CONVERT(0);  CONVERT(1);
    LOAD_RAW(2); LOAD_RAW(3);
    PF(4); PF(5);

    u64 mAcc0 = f2_set(0.f), mAcc1 = f2_set(0.f);
    float sA0 = 0.f, sA1 = 0.f;

#pragma unroll
    for (int r = 0; r < RPW; r += 2) {
        const int jA = r & 3, jB = (r + 1) & 3, jC = (r + 2) & 3, jD = (r + 3) & 3;

        // (1) convert row r+2 (raw since last iteration; loads long done)
        CONVERT(r + 2);

        // (2) halo partials + A-row halo sums
        u64 hA = whsd[jA], hB = whsd[jB], hC = whsd[jC];
        u64 hp  = add2(hB, hC);
        u64 hq  = fma2(hB, hB, mul2(hC, hC));
        u64 vh1A = add2(hp, hA);
        u64 vh2A = fma2(hA, hA, hq);
        float vHsA, vHdA, vHssA, vHddA;
        f2_unpack(vh1A, vHsA, vHdA);
        f2_unpack(vh2A, vHssA, vHddA);

        // (2b) shared middle-pair partials: linear AND squares
        u64 ps[4], pd[4], qs[4], qd[4];
#pragma unroll
        for (int k = 0; k < 4; ++k) {
            u64 sB = ws[jB][k],  sC = ws[jC][k];
            u64 dB = wdv[jB][k], dC = wdv[jC][k];
            ps[k] = add2(sB, sC);
            pd[k] = add2(dB, dC);
            qs[k] = fma2(sB, sB, mul2(sC, sC));
            qd[k] = fma2(dB, dB, mul2(dC, dC));
        }

        // (2c) MSE of center rows B,C comes free from qd
        mAcc0 = add2(mAcc0, qd[0]);
        mAcc0 = add2(mAcc0, qd[1]);
        mAcc1 = add2(mAcc1, qd[2]);
        mAcc1 = add2(mAcc1, qd[3]);

        // one output row; jx = its distinct window slot
        auto ROW = [&](int jx, float vHs, float vHd, float vHss, float vHdd) {
            u64 T1[4], T2[4];
            {
                u64 Vq[4], Hq[4];
#pragma unroll
                for (int k = 0; k < 4; ++k) Vq[k] = add2(ps[k], ws[jx][k]);
                hsum8(Vq[0], Vq[1], Vq[2], Vq[3], vHs, lane, half,
                      Hq[0], Hq[1], Hq[2], Hq[3]);
                u64 Es[4];
#pragma unroll
                for (int k = 0; k < 4; ++k) Es[k] = mul2(Hq[k], Hq[k]);
#pragma unroll
                for (int k = 0; k < 4; ++k) Vq[k] = add2(pd[k], wdv[jx][k]);
                hsum8(Vq[0], Vq[1], Vq[2], Vq[3], vHd, lane, half,
                      Hq[0], Hq[1], Hq[2], Hq[3]);
#pragma unroll
                for (int k = 0; k < 4; ++k) {
                    u64 F = mul2(Hq[k], Hq[k]);
                    T1[k] = sub2(Es[k], F);
                    T2[k] = add2(Es[k], F);
                }
            }
            u64 Hss[4], Hdd[4];
            {
                u64 Vq[4];
#pragma unroll
                for (int k = 0; k < 4; ++k)
                    Vq[k] = fma2(ws[jx][k], ws[jx][k], qs[k]);
                hsum8(Vq[0], Vq[1], Vq[2], Vq[3], vHss, lane, half,
                      Hss[0], Hss[1], Hss[2], Hss[3]);
#pragma unroll
                for (int k = 0; k < 4; ++k)
                    Vq[k] = fma2(wdv[jx][k], wdv[jx][k], qd[k]);
                hsum8(Vq[0], Vq[1], Vq[2], Vq[3], vHdd, lane, half,
                      Hdd[0], Hdd[1], Hdd[2], Hdd[3]);
            }
#pragma unroll
            for (int k = 0; k < 4; ++k) {
                u64 N1 = add2(T1[k], kC1);
                u64 D1 = add2(T2[k], kC1);
                u64 U1 = sub2(Hss[k], Hdd[k]);
                u64 U2 = add2(Hss[k], Hdd[k]);
                u64 N2 = sub2(fma2(U1, k9, kC2), T1[k]);
                u64 D2 = sub2(fma2(U2, k9, kC2), T2[k]);
                u64 num = mul2(N1, N2);
                u64 den = fma2(D1, D2, kEPS);
                float n0, n1, d0, d1;
                f2_unpack(num, n0, n1);
                f2_unpack(den, d0, d1);
                // paired division: one MUFU per 2 quotients
                float nc = fmaf(n0, d1, n1 * d0);
                float dc = d0 * d1;
                if (k & 1) sA1 += __fdividef(nc, dc);
                else       sA0 += __fdividef(nc, dc);
            }
        };

        // (3) output row r : needs slots jA,jB,jC (all converted)
        ROW(jA, vHsA, vHdA, vHssA, vHddA);

        // (4) slot jA retired -> load row r+4 raw
        if (r < RPW - 2) LOAD_RAW(r + 4);

        // (5) convert row r+3; B-row halo sums
        CONVERT(r + 3);
        u64 hD = whsd[jD];
        u64 vh1B = add2(hp, hD);
        u64 vh2B = fma2(hD, hD, hq);
        float vHsB, vHdB, vHssB, vHddB;
        f2_unpack(vh1B, vHsB, vHdB);
        f2_unpack(vh2B, vHssB, vHddB);

        // (6) output row r+1 : needs slots jB,jC,jD
        ROW(jD, vHsB, vHdB, vHssB, vHddB);

        // (7) slot jB retired -> load row r+5 raw; hints beyond
        if (r < RPW - 2) {
            LOAD_RAW(r + 5);
            PF(r + 6); PF(r + 7);
        }
    }

    // ---- reductions ----
    float m0, m1, m2, m3;
    f2_unpack(mAcc0, m0, m1);
    f2_unpack(mAcc1, m2, m3);
    float mAcc = (m0 + m1) + (m2 + m3);
    float sAcc = sA0 + sA1;
#pragma unroll
    for (int o = 16; o; o >>= 1) {
        mAcc += __shfl_xor_sync(0xffffffffu, mAcc, o);
        sAcc += __shfl_xor_sync(0xffffffffu, sAcc, o);
    }
    __shared__ float shm[WPB], shs[WPB];
    if (lane == 0) { shm[w] = mAcc; shs[w] = sAcc; }
    __syncthreads();
    if (threadIdx.x == 0) {
        float M = (shm[0] + shm[1]) + (shm[2] + shm[3]);
        float S = (shs[0] + shs[1]) + (shs[2] + shs[3]);
        atomicAdd(&g_mse_acc, M);
        atomicAdd(&g_ssim_acc, S);
        __threadfence();
        unsigned c = atomicInc(&g_cnt, NBLOCKS - 1);   // wraps to 0 on last
        if (c == NBLOCKS - 1) {
            __threadfence();
            float Mt = atomicExch(&g_mse_acc, 0.f);
            float St = atomicExch(&g_ssim_acc, 0.f);
            double mse  = (double)Mt / NTOTD;
            double ssim = (double)St / NTOTD;
            out[0] = (float)(0.8 * mse + 0.2 * (1.0 - ssim));
        }
    }
}

extern "C" void kernel_launch(void* const* d_in, const int* in_sizes, int n_in,
                              void* d_out, int out_size) {
    const float* X = (const float*)d_in[0];
    const float* Y = (const float*)d_in[1];
    loss_fused<<<NBLOCKS, 128>>>(X, Y, (float*)d_out);
}

// round 15
// speedup vs baseline: 1.5163x; 1.0137x over previous
#include <cuda_runtime.h>

// ---------------------------------------------------------------------------
// EnhancedReconstructionLoss: 0.8*MSE + 0.2*(1 - mean(SSIM_map)), fused.
//
// s/d reformulation (s=x+y, d=x-y) -> 4 window sums (Ws,Wd,Wss,Wdd):
//   N1 = (Ws^2-Wd^2) + 162*C1          N2 = 9(Wss-Wdd) - (Ws^2-Wd^2) + 162*C2
//   D1 = (Ws^2+Wd^2) + 162*C1          D2 = 9(Wss+Wdd) - (Ws^2+Wd^2) + 162*C2
//   ssim = N1*N2 / (D1*D2 + 4*6561*eps)
//
// R15 = R14 body on 4-cols/lane geometry: halved window (32 regs), halved
// transients -> ~100 regs -> 5 CTAs/SM (20 warps, +25%) AND shorter chains
// ptxas can overlap. Raw-slot decoupled loads, in-place converts, shared
// pair squares, MSE from qd, paired division, PF hints all carried over.
// ---------------------------------------------------------------------------

typedef unsigned long long u64;

#define IMW 512
#define IMH 512
#define NPLANES 96
#define RPW 16                    // rows per warp-task
#define STRIPS 32                 // 512 / 16
#define QCOLS 4                   // warp-columns (128 cols per warp)
#define WPB 4                     // warps per block
#define NBLOCKS (NPLANES * STRIPS * QCOLS / WPB)   // 3072
#define NTOTD 25165824.0          // 32*3*512*512

__device__ float g_mse_acc  = 0.f;
__device__ float g_ssim_acc = 0.f;
__device__ unsigned int g_cnt = 0u;

__device__ __forceinline__ u64 f2_pack(float lo, float hi) {
    u64 r; asm("mov.b64 %0, {%1, %2};" : "=l"(r) : "f"(lo), "f"(hi)); return r;
}
__device__ __forceinline__ void f2_unpack(u64 p, float& lo, float& hi) {
    asm("mov.b64 {%0, %1}, %2;" : "=f"(lo), "=f"(hi) : "l"(p));
}
__device__ __forceinline__ u64 f2_set(float v) { return f2_pack(v, v); }
__device__ __forceinline__ u64 add2(u64 a, u64 b) {
    u64 d; asm("add.rn.f32x2 %0, %1, %2;" : "=l"(d) : "l"(a), "l"(b)); return d;
}
__device__ __forceinline__ u64 sub2(u64 a, u64 b) {
    u64 d; asm("sub.rn.f32x2 %0, %1, %2;" : "=l"(d) : "l"(a), "l"(b)); return d;
}
__device__ __forceinline__ u64 mul2(u64 a, u64 b) {
    u64 d; asm("mul.rn.f32x2 %0, %1, %2;" : "=l"(d) : "l"(a), "l"(b)); return d;
}
__device__ __forceinline__ u64 fma2(u64 a, u64 b, u64 c) {
    u64 d; asm("fma.rn.f32x2 %0, %1, %2, %3;" : "=l"(d) : "l"(a), "l"(b), "l"(c)); return d;
}

// Horizontal 3-sum over 4 columns (2 packed u64). vH = this lane's halo value
// (left for lane 0, right for lane 31; zero at image edges).
__device__ __forceinline__ void hsum4(u64 v0, u64 v1, float vH, int lane,
                                      u64& H0, u64& H1) {
    float f0, f1, f2, f3;
    f2_unpack(v0, f0, f1);
    f2_unpack(v1, f2, f3);
    float up = __shfl_up_sync(0xffffffffu, f3, 1);
    float dn = __shfl_down_sync(0xffffffffu, f0, 1);
    float nl = (lane == 0)  ? vH : up;
    float nr = (lane == 31) ? vH : dn;
    u64 L0 = f2_pack(nl, f0);
    u64 L1 = f2_pack(f1, f2);
    u64 R1 = f2_pack(f3, nr);
    H0 = add2(add2(L0, v0), L1);
    H1 = add2(add2(L1, v1), R1);
}

__global__ void __launch_bounds__(128, 5)
loss_fused(const float* __restrict__ X, const float* __restrict__ Y,
           float* __restrict__ out) {
    const int w    = threadIdx.x >> 5;
    const int lane = threadIdx.x & 31;
    const int task  = blockIdx.x * WPB + w;
    const int qcol  = task & (QCOLS - 1);
    const int strip = (task >> 2) & (STRIPS - 1);
    const int plane = task >> 7;
    const int R0 = strip * RPW;
    const int c0 = qcol * 128 + (lane << 2);

    const float* px = X + (size_t)plane * (IMW * IMH) + c0;
    const float* py = Y + (size_t)plane * (IMW * IMH) + c0;

    const bool hval = (lane == 0) ? (qcol > 0)
                    : ((lane == 31) ? (qcol < QCOLS - 1) : false);
    const int hoff = (lane == 0) ? -1 : 4;

    const u64 k9   = f2_set(9.0f);
    const u64 kC1  = f2_set(0.0162f);      // 162 * C1
    const u64 kC2  = f2_set(0.1458f);      // 162 * C2
    const u64 kEPS = f2_set(2.6244e-4f);   // 4 * 6561 * eps

    // 4-slot rolling window: RAW (x,y) until CONVERTed in place to (s,d).
    u64 ws[4][2], wdv[4][2];
    u64 whsd[4];

    auto PF = [&](int j) {
        int gr = R0 - 1 + j;
        gr = (gr < IMH) ? gr : (IMH - 1);
        const float* ax = px + (size_t)gr * IMW;
        const float* ay = py + (size_t)gr * IMW;
        asm volatile("prefetch.global.L2 [%0];" :: "l"(ax));
        asm volatile("prefetch.global.L2 [%0];" :: "l"(ay));
    };

    // Load row gr = R0-1+j RAW into slot j&3 (pure LDG + pack).
    auto LOAD_RAW = [&](int j) {
        const int slot = j & 3;
        const int gr = R0 - 1 + j;
        const bool v = ((unsigned)gr < (unsigned)IMH);
        float4 xa = make_float4(0.f, 0.f, 0.f, 0.f), ya = xa;
        float hx = 0.f, hy = 0.f;
        if (v) {
            xa = *reinterpret_cast<const float4*>(px + (size_t)gr * IMW);
            ya = *reinterpret_cast<const float4*>(py + (size_t)gr * IMW);
            if (hval) {
                hx = px[(size_t)gr * IMW + hoff];
                hy = py[(size_t)gr * IMW + hoff];
            }
        }
        ws[slot][0]  = f2_pack(xa.x, xa.y);  ws[slot][1]  = f2_pack(xa.z, xa.w);
        wdv[slot][0] = f2_pack(ya.x, ya.y);  wdv[slot][1] = f2_pack(ya.z, ya.w);
        whsd[slot]   = f2_pack(hx, hy);
    };

    // In-place convert slot j&3 from raw (x,y) to (s,d).
    auto CONVERT = [&](int j) {
        const int slot = j & 3;
#pragma unroll
        for (int k = 0; k < 2; ++k) {
            u64 xv = ws[slot][k], yv = wdv[slot][k];
            ws[slot][k]  = add2(xv, yv);
            wdv[slot][k] = sub2(xv, yv);
        }
        float hx, hy;
        f2_unpack(whsd[slot], hx, hy);
        whsd[slot] = f2_pack(hx + hy, hx - hy);
    };

    LOAD_RAW(0); LOAD_RAW(1);
    CONVERT(0);  CONVERT(1);
    LOAD_RAW(2); LOAD_RAW(3);
    PF(4); PF(5);

    u64 mAcc0 = f2_set(0.f), mAcc1 = f2_set(0.f);
    float sA0 = 0.f, sA1 = 0.f;

#pragma unroll
    for (int r = 0; r < RPW; r += 2) {
        const int jA = r & 3, jB = (r + 1) & 3, jC = (r + 2) & 3, jD = (r + 3) & 3;

        // (1) convert row r+2 (raw since last iteration; loads long done)
        CONVERT(r + 2);

        // (2) halo partials + A-row halo sums
        u64 hA = whsd[jA], hB = whsd[jB], hC = whsd[jC];
        u64 hp  = add2(hB, hC);
        u64 hq  = fma2(hB, hB, mul2(hC, hC));
        u64 vh1A = add2(hp, hA);
        u64 vh2A = fma2(hA, hA, hq);
        float vHsA, vHdA, vHssA, vHddA;
        f2_unpack(vh1A, vHsA, vHdA);
        f2_unpack(vh2A, vHssA, vHddA);

        // (2b) shared middle-pair partials: linear AND squares
        u64 ps[2], pd[2], qs[2], qd[2];
#pragma unroll
        for (int k = 0; k < 2; ++k) {
            u64 sB = ws[jB][k],  sC = ws[jC][k];
            u64 dB = wdv[jB][k], dC = wdv[jC][k];
            ps[k] = add2(sB, sC);
            pd[k] = add2(dB, dC);
            qs[k] = fma2(sB, sB, mul2(sC, sC));
            qd[k] = fma2(dB, dB, mul2(dC, dC));
        }

        // (2c) MSE of center rows B,C comes free from qd
        mAcc0 = add2(mAcc0, qd[0]);
        mAcc1 = add2(mAcc1, qd[1]);

        // one output row; jx = its distinct window slot
        auto ROW = [&](int jx, float vHs, float vHd, float vHss, float vHdd) {
            u64 T1[2], T2[2];
            {
                u64 Vq[2], Hq[2];
                Vq[0] = add2(ps[0], ws[jx][0]);
                Vq[1] = add2(ps[1], ws[jx][1]);
                hsum4(Vq[0], Vq[1], vHs, lane, Hq[0], Hq[1]);
                u64 Es[2];
                Es[0] = mul2(Hq[0], Hq[0]);
                Es[1] = mul2(Hq[1], Hq[1]);
                Vq[0] = add2(pd[0], wdv[jx][0]);
                Vq[1] = add2(pd[1], wdv[jx][1]);
                hsum4(Vq[0], Vq[1], vHd, lane, Hq[0], Hq[1]);
#pragma unroll
                for (int k = 0; k < 2; ++k) {
                    u64 F = mul2(Hq[k], Hq[k]);
                    T1[k] = sub2(Es[k], F);
                    T2[k] = add2(Es[k], F);
                }
            }
            u64 Hss[2], Hdd[2];
            {
                u64 Vq[2];
                Vq[0] = fma2(ws[jx][0], ws[jx][0], qs[0]);
                Vq[1] = fma2(ws[jx][1], ws[jx][1], qs[1]);
                hsum4(Vq[0], Vq[1], vHss, lane, Hss[0], Hss[1]);
                Vq[0] = fma2(wdv[jx][0], wdv[jx][0], qd[0]);
                Vq[1] = fma2(wdv[jx][1], wdv[jx][1], qd[1]);
                hsum4(Vq[0], Vq[1], vHdd, lane, Hdd[0], Hdd[1]);
            }
#pragma unroll
            for (int k = 0; k < 2; ++k) {
                u64 N1 = add2(T1[k], kC1);
                u64 D1 = add2(T2[k], kC1);
                u64 U1 = sub2(Hss[k], Hdd[k]);
                u64 U2 = add2(Hss[k], Hdd[k]);
                u64 N2 = sub2(fma2(U1, k9, kC2), T1[k]);
                u64 D2 = sub2(fma2(U2, k9, kC2), T2[k]);
                u64 num = mul2(N1, N2);
                u64 den = fma2(D1, D2, kEPS);
                float n0, n1, d0, d1;
                f2_unpack(num, n0, n1);
                f2_unpack(den, d0, d1);
                // paired division: one MUFU per 2 quotients
                float nc = fmaf(n0, d1, n1 * d0);
                float dc = d0 * d1;
                if (k) sA1 += __fdividef(nc, dc);
                else   sA0 += __fdividef(nc, dc);
            }
        };

        // (3) output row r : needs slots jA,jB,jC (all converted)
        ROW(jA, vHsA, vHdA, vHssA, vHddA);

        // (4) slot jA retired -> load row r+4 raw
        if (r < RPW - 2) LOAD_RAW(r + 4);

        // (5) convert row r+3; B-row halo sums
        CONVERT(r + 3);
        u64 hD = whsd[jD];
        u64 vh1B = add2(hp, hD);
        u64 vh2B = fma2(hD, hD, hq);
        float vHsB, vHdB, vHssB, vHddB;
        f2_unpack(vh1B, vHsB, vHdB);
        f2_unpack(vh2B, vHssB, vHddB);

        // (6) output row r+1 : needs slots jB,jC,jD
        ROW(jD, vHsB, vHdB, vHssB, vHddB);

        // (7) slot jB retired -> load row r+5 raw; hints beyond
        if (r < RPW - 2) {
            LOAD_RAW(r + 5);
            PF(r + 6); PF(r + 7);
        }
    }

    // ---- reductions ----
    float m0, m1, m2, m3;
    f2_unpack(mAcc0, m0, m1);
    f2_unpack(mAcc1, m2, m3);
    float mAcc = (m0 + m1) + (m2 + m3);
    float sAcc = sA0 + sA1;
#pragma unroll
    for (int o = 16; o; o >>= 1) {
        mAcc += __shfl_xor_sync(0xffffffffu, mAcc, o);
        sAcc += __shfl_xor_sync(0xffffffffu, sAcc, o);
    }
    __shared__ float shm[WPB], shs[WPB];
    if (lane == 0) { shm[w] = mAcc; shs[w] = sAcc; }
    __syncthreads();
    if (threadIdx.x == 0) {
        float M = (shm[0] + shm[1]) + (shm[2] + shm[3]);
        float S = (shs[0] + shs[1]) + (shs[2] + shs[3]);
        atomicAdd(&g_mse_acc, M);
        atomicAdd(&g_ssim_acc, S);
        __threadfence();
        unsigned c = atomicInc(&g_cnt, NBLOCKS - 1);   // wraps to 0 on last
        if (c == NBLOCKS - 1) {
            __threadfence();
            float Mt = atomicExch(&g_mse_acc, 0.f);
            float St = atomicExch(&g_ssim_acc, 0.f);
            double mse  = (double)Mt / NTOTD;
            double ssim = (double)St / NTOTD;
            out[0] = (float)(0.8 * mse + 0.2 * (1.0 - ssim));
        }
    }
}

extern "C" void kernel_launch(void* const* d_in, const int* in_sizes, int n_in,
                              void* d_out, int out_size) {
    const float* X = (const float*)d_in[0];
    const float* Y = (const float*)d_in[1];
    loss_fused<<<NBLOCKS, 128>>>(X, Y, (float*)d_out);
}